// round 2
// baseline (speedup 1.0000x reference)
#include <cuda_runtime.h>
#include <cuda_bf16.h>
#include <cstdint>

// Problem constants
#define NB 2
#define TT 4096
#define DM 768
#define NH 12
#define DH 64
#define MROWS (NB * TT)   // 8192

// Scratch in __device__ globals (allocation-free rule)
__device__ float g_q[(size_t)NB * NH * TT * DH];
__device__ float g_k[(size_t)NB * NH * TT * DH];
__device__ float g_v[(size_t)NB * NH * TT * DH];
__device__ float g_a[(size_t)NB * TT * DM];
__device__ float g_maskf[(size_t)NB * TT];

// ---------------------------------------------------------------------------
// Mask (bool serialized as int32) -> additive float bias (0 or -1e30)
// ---------------------------------------------------------------------------
__global__ void mask_to_f_kernel(const int* __restrict__ mask,
                                 float* __restrict__ out, int n) {
    int i = blockIdx.x * blockDim.x + threadIdx.x;
    if (i < n) out[i] = mask[i] ? -1e30f : 0.0f;
}

// ---------------------------------------------------------------------------
// C = A @ B^T + bias.  A: [M,768] row-major. B: [768,768] row-major (torch W).
// MODE 0: C[m, col] plain [M, 768]  (used for output projection -> d_out)
// MODE 1: C written head-split as [n, h, t, dh]  (used for Q/K/V)
// Tile: 64x64, BK=16, 256 threads, 4x4 microtile.
// ---------------------------------------------------------------------------
template <int MODE>
__global__ __launch_bounds__(256)
void gemm_abt_kernel(const float* __restrict__ A, const float* __restrict__ B,
                     const float* __restrict__ bias, float* __restrict__ C) {
    __shared__ float As[16][64];
    __shared__ float Bs[16][64];

    const int tx = threadIdx.x & 15;       // 0..15 (col group)
    const int ty = threadIdx.x >> 4;       // 0..15 (row group)
    const int row0 = blockIdx.x * 64;
    const int col0 = blockIdx.y * 64;

    const int lrow = threadIdx.x >> 2;          // 0..63 load row
    const int lk4  = (threadIdx.x & 3) * 4;     // 0,4,8,12 load k base

    float acc[4][4];
#pragma unroll
    for (int i = 0; i < 4; i++)
#pragma unroll
        for (int q = 0; q < 4; q++) acc[i][q] = 0.0f;

    for (int k0 = 0; k0 < DM; k0 += 16) {
        float4 a4 = *reinterpret_cast<const float4*>(
            &A[(size_t)(row0 + lrow) * DM + k0 + lk4]);
        float4 b4 = *reinterpret_cast<const float4*>(
            &B[(size_t)(col0 + lrow) * DM + k0 + lk4]);

        As[lk4 + 0][lrow] = a4.x;
        As[lk4 + 1][lrow] = a4.y;
        As[lk4 + 2][lrow] = a4.z;
        As[lk4 + 3][lrow] = a4.w;
        Bs[lk4 + 0][lrow] = b4.x;
        Bs[lk4 + 1][lrow] = b4.y;
        Bs[lk4 + 2][lrow] = b4.z;
        Bs[lk4 + 3][lrow] = b4.w;
        __syncthreads();

#pragma unroll
        for (int k = 0; k < 16; k++) {
            float4 av = *reinterpret_cast<float4*>(&As[k][ty * 4]);
            float4 bv = *reinterpret_cast<float4*>(&Bs[k][tx * 4]);
            float ar[4] = {av.x, av.y, av.z, av.w};
            float br[4] = {bv.x, bv.y, bv.z, bv.w};
#pragma unroll
            for (int i = 0; i < 4; i++)
#pragma unroll
                for (int q = 0; q < 4; q++) acc[i][q] += ar[i] * br[q];
        }
        __syncthreads();
    }

    // Epilogue
#pragma unroll
    for (int i = 0; i < 4; i++) {
        int row = row0 + ty * 4 + i;
        float4 res;
        res.x = acc[i][0] + bias[col0 + tx * 4 + 0];
        res.y = acc[i][1] + bias[col0 + tx * 4 + 1];
        res.z = acc[i][2] + bias[col0 + tx * 4 + 2];
        res.w = acc[i][3] + bias[col0 + tx * 4 + 3];
        if (MODE == 0) {
            *reinterpret_cast<float4*>(&C[(size_t)row * DM + col0 + tx * 4]) = res;
        } else {
            int n = row >> 12;        // / TT
            int t = row & (TT - 1);   // % TT
            int h = blockIdx.y;       // col0/64
            size_t idx = (((size_t)(n * NH + h)) * TT + t) * DH + tx * 4;
            *reinterpret_cast<float4*>(&C[idx]) = res;
        }
    }
}

// ---------------------------------------------------------------------------
// Flash attention, fp32. One CTA = 64 queries of one (n,h).
// 256 threads: thread (r = tid>>2, j = tid&3) owns s/p cols [j*16, j*16+16)
// and O dims [j*16, j*16+16) of query row r.
// Smem: Qs 16KB, Ks 16KB (reused for P), Vs 16KB == 48KB static.
// ---------------------------------------------------------------------------
__global__ __launch_bounds__(256)
void flash_attn_kernel(const float* __restrict__ Qg, const float* __restrict__ Kg,
                       const float* __restrict__ Vg, const float* __restrict__ mbf,
                       float* __restrict__ Ag) {
    __shared__ float Qs[64 * 64];
    __shared__ float Ks[64 * 64];   // reused as P after S computed
    __shared__ float Vs[64 * 64];

    const int n = blockIdx.z, h = blockIdx.y;
    const int q0 = blockIdx.x * 64;
    const size_t headBase = ((size_t)(n * NH + h)) * TT * DH;
    const float* Qb = Qg + headBase + (size_t)q0 * DH;
    const float* Kb = Kg + headBase;
    const float* Vb = Vg + headBase;
    const float* mb = mbf + (size_t)n * TT;

    const int tid = threadIdx.x;
    const int r = tid >> 2;   // query row 0..63
    const int j = tid & 3;    // segment 0..3

    // Load Q tile
    for (int i = tid; i < 1024; i += 256)
        reinterpret_cast<float4*>(Qs)[i] = reinterpret_cast<const float4*>(Qb)[i];
    __syncthreads();

    float o[16];
#pragma unroll
    for (int i = 0; i < 16; i++) o[i] = 0.0f;
    float m = -1e30f, l = 0.0f;
    const float sc = 0.125f;  // 1/sqrt(64)

    for (int kb = 0; kb < TT / 64; kb++) {
        const int c0 = kb * 64;
        // Skip fully-masked key tiles (also serves as the end-of-iter barrier)
        float mv = (tid < 64) ? mb[c0 + tid] : -1.0f;
        int alive = __syncthreads_count((tid < 64) && (mv == 0.0f));
        if (alive == 0) continue;

        // Load K, V tiles (contiguous [64,64])
        const float4* ksrc = reinterpret_cast<const float4*>(Kb + (size_t)c0 * DH);
        const float4* vsrc = reinterpret_cast<const float4*>(Vb + (size_t)c0 * DH);
        for (int i = tid; i < 1024; i += 256) {
            reinterpret_cast<float4*>(Ks)[i] = ksrc[i];
            reinterpret_cast<float4*>(Vs)[i] = vsrc[i];
        }
        __syncthreads();

        // S = Q K^T for my 16 columns
        float s[16];
#pragma unroll
        for (int c = 0; c < 16; c++) s[c] = 0.0f;
#pragma unroll
        for (int d = 0; d < 64; d += 4) {
            float4 q4 = *reinterpret_cast<float4*>(&Qs[r * 64 + d]);
#pragma unroll
            for (int c = 0; c < 16; c++) {
                float4 k4 = *reinterpret_cast<float4*>(&Ks[(j * 16 + c) * 64 + d]);
                s[c] += q4.x * k4.x + q4.y * k4.y + q4.z * k4.z + q4.w * k4.w;
            }
        }
        // scale + additive mask
#pragma unroll
        for (int c4 = 0; c4 < 4; c4++) {
            float4 madd = reinterpret_cast<const float4*>(mb + c0 + j * 16)[c4];
            s[c4 * 4 + 0] = s[c4 * 4 + 0] * sc + madd.x;
            s[c4 * 4 + 1] = s[c4 * 4 + 1] * sc + madd.y;
            s[c4 * 4 + 2] = s[c4 * 4 + 2] * sc + madd.z;
            s[c4 * 4 + 3] = s[c4 * 4 + 3] * sc + madd.w;
        }

        // Row max across the 4 threads of this row (lanes differ in bits 0..1)
        float tmax = s[0];
#pragma unroll
        for (int c = 1; c < 16; c++) tmax = fmaxf(tmax, s[c]);
        tmax = fmaxf(tmax, __shfl_xor_sync(0xffffffffu, tmax, 1));
        tmax = fmaxf(tmax, __shfl_xor_sync(0xffffffffu, tmax, 2));

        float mn = fmaxf(m, tmax);
        float corr = __expf(m - mn);
        float ssum = 0.0f;
#pragma unroll
        for (int c = 0; c < 16; c++) {
            float p = __expf(s[c] - mn);
            s[c] = p;
            ssum += p;
        }
        ssum += __shfl_xor_sync(0xffffffffu, ssum, 1);
        ssum += __shfl_xor_sync(0xffffffffu, ssum, 2);
        l = l * corr + ssum;
        m = mn;
#pragma unroll
        for (int i = 0; i < 16; i++) o[i] *= corr;

        __syncthreads();              // all K reads done before overwriting as P
#pragma unroll
        for (int c = 0; c < 16; c++) Ks[r * 64 + j * 16 + c] = s[c];
        __syncthreads();

        // O += P @ V  (my 16 dh columns)
#pragma unroll 8
        for (int c = 0; c < 64; c++) {
            float p = Ks[r * 64 + c];
            const float4* vr = reinterpret_cast<const float4*>(&Vs[c * 64 + j * 16]);
            float4 v0 = vr[0], v1 = vr[1], v2 = vr[2], v3 = vr[3];
            o[0]  += p * v0.x; o[1]  += p * v0.y; o[2]  += p * v0.z; o[3]  += p * v0.w;
            o[4]  += p * v1.x; o[5]  += p * v1.y; o[6]  += p * v1.z; o[7]  += p * v1.w;
            o[8]  += p * v2.x; o[9]  += p * v2.y; o[10] += p * v2.z; o[11] += p * v2.w;
            o[12] += p * v3.x; o[13] += p * v3.y; o[14] += p * v3.z; o[15] += p * v3.w;
        }
        // next iteration's __syncthreads_count protects Ks/Vs reuse
    }

    // Normalize and write to [n, t, h*64 + ...] (concat-head layout)
    float inv = 1.0f / l;
    size_t obase = ((size_t)n * TT + q0 + r) * DM + h * DH + j * 16;
    float4* op = reinterpret_cast<float4*>(Ag + obase);
#pragma unroll
    for (int w = 0; w < 4; w++) {
        float4 res;
        res.x = o[w * 4 + 0] * inv;
        res.y = o[w * 4 + 1] * inv;
        res.z = o[w * 4 + 2] * inv;
        res.w = o[w * 4 + 3] * inv;
        op[w] = res;
    }
}

// ---------------------------------------------------------------------------
// Launch
// ---------------------------------------------------------------------------
extern "C" void kernel_launch(void* const* d_in, const int* in_sizes, int n_in,
                              void* d_out, int out_size) {
    const float* x  = (const float*)d_in[0];
    const int*   mask = (const int*)d_in[1];
    const float* Wq = (const float*)d_in[2];
    const float* bq = (const float*)d_in[3];
    const float* Wk = (const float*)d_in[4];
    const float* bk = (const float*)d_in[5];
    const float* Wv = (const float*)d_in[6];
    const float* bv = (const float*)d_in[7];
    const float* Wo = (const float*)d_in[8];
    const float* bo = (const float*)d_in[9];
    float* out = (float*)d_out;

    float *q, *k, *v, *a, *mf;
    cudaGetSymbolAddress((void**)&q,  g_q);
    cudaGetSymbolAddress((void**)&k,  g_k);
    cudaGetSymbolAddress((void**)&v,  g_v);
    cudaGetSymbolAddress((void**)&a,  g_a);
    cudaGetSymbolAddress((void**)&mf, g_maskf);

    mask_to_f_kernel<<<(NB * TT + 255) / 256, 256>>>(mask, mf, NB * TT);

    dim3 ggrid(MROWS / 64, DM / 64);
    gemm_abt_kernel<1><<<ggrid, 256>>>(x, Wq, bq, q);
    gemm_abt_kernel<1><<<ggrid, 256>>>(x, Wk, bk, k);
    gemm_abt_kernel<1><<<ggrid, 256>>>(x, Wv, bv, v);

    dim3 agrid(TT / 64, NH, NB);
    flash_attn_kernel<<<agrid, 256>>>(q, k, v, mf, a);

    gemm_abt_kernel<0><<<ggrid, 256>>>(a, Wo, bo, out);
}

// round 3
// speedup vs baseline: 4.4089x; 4.4089x over previous
#include <cuda_runtime.h>
#include <cuda_bf16.h>
#include <cstdint>

// Problem constants
#define NB 2
#define TT 4096
#define DM 768
#define NH 12
#define DH 64
#define MROWS (NB * TT)   // 8192

// Scratch in __device__ globals (allocation-free rule)
__device__ float g_q[(size_t)NB * NH * TT * DH];
__device__ float g_k[(size_t)NB * NH * TT * DH];
__device__ float g_v[(size_t)NB * NH * TT * DH];
__device__ float g_a[(size_t)NB * TT * DM];
__device__ float g_maskf[(size_t)NB * TT];

// Swizzled index into a 64x64 float tile: element [row][col], float4-group XOR
// swizzle in col keyed by row>>2 (keeps 16B alignment for float4 ops).
__device__ __forceinline__ int TIDX(int row, int col) {
    return row * 64 + (((((col) >> 2) ^ ((row >> 2) & 7)) << 2) | (col & 3));
}

// ---------------------------------------------------------------------------
// Mask (bool serialized as int32) -> additive float bias (0 or -1e30)
// ---------------------------------------------------------------------------
__global__ void mask_to_f_kernel(const int* __restrict__ mask,
                                 float* __restrict__ out, int n) {
    int i = blockIdx.x * blockDim.x + threadIdx.x;
    if (i < n) out[i] = mask[i] ? -1e30f : 0.0f;
}

// ---------------------------------------------------------------------------
// C = A @ B^T + bias.  A: [M,768] row-major. B: [768,768] row-major (torch W).
// MODE 0: C[m, col] plain [M, 768]  (output projection -> d_out)
// MODE 1: C written head-split as [n, h, t, dh]  (Q/K/V)
// ---------------------------------------------------------------------------
template <int MODE>
__global__ __launch_bounds__(256)
void gemm_abt_kernel(const float* __restrict__ A, const float* __restrict__ B,
                     const float* __restrict__ bias, float* __restrict__ C) {
    __shared__ float As[16][64];
    __shared__ float Bs[16][64];

    const int tx = threadIdx.x & 15;
    const int ty = threadIdx.x >> 4;
    const int row0 = blockIdx.x * 64;
    const int col0 = blockIdx.y * 64;

    const int lrow = threadIdx.x >> 2;
    const int lk4  = (threadIdx.x & 3) * 4;

    float acc[4][4];
#pragma unroll
    for (int i = 0; i < 4; i++)
#pragma unroll
        for (int q = 0; q < 4; q++) acc[i][q] = 0.0f;

    for (int k0 = 0; k0 < DM; k0 += 16) {
        float4 a4 = *reinterpret_cast<const float4*>(
            &A[(size_t)(row0 + lrow) * DM + k0 + lk4]);
        float4 b4 = *reinterpret_cast<const float4*>(
            &B[(size_t)(col0 + lrow) * DM + k0 + lk4]);

        As[lk4 + 0][lrow] = a4.x;
        As[lk4 + 1][lrow] = a4.y;
        As[lk4 + 2][lrow] = a4.z;
        As[lk4 + 3][lrow] = a4.w;
        Bs[lk4 + 0][lrow] = b4.x;
        Bs[lk4 + 1][lrow] = b4.y;
        Bs[lk4 + 2][lrow] = b4.z;
        Bs[lk4 + 3][lrow] = b4.w;
        __syncthreads();

#pragma unroll
        for (int k = 0; k < 16; k++) {
            float4 av = *reinterpret_cast<float4*>(&As[k][ty * 4]);
            float4 bv = *reinterpret_cast<float4*>(&Bs[k][tx * 4]);
            float ar[4] = {av.x, av.y, av.z, av.w};
            float br[4] = {bv.x, bv.y, bv.z, bv.w};
#pragma unroll
            for (int i = 0; i < 4; i++)
#pragma unroll
                for (int q = 0; q < 4; q++) acc[i][q] += ar[i] * br[q];
        }
        __syncthreads();
    }

#pragma unroll
    for (int i = 0; i < 4; i++) {
        int row = row0 + ty * 4 + i;
        float4 res;
        res.x = acc[i][0] + bias[col0 + tx * 4 + 0];
        res.y = acc[i][1] + bias[col0 + tx * 4 + 1];
        res.z = acc[i][2] + bias[col0 + tx * 4 + 2];
        res.w = acc[i][3] + bias[col0 + tx * 4 + 3];
        if (MODE == 0) {
            *reinterpret_cast<float4*>(&C[(size_t)row * DM + col0 + tx * 4]) = res;
        } else {
            int n = row >> 12;
            int t = row & (TT - 1);
            int h = blockIdx.y;
            size_t idx = (((size_t)(n * NH + h)) * TT + t) * DH + tx * 4;
            *reinterpret_cast<float4*>(&C[idx]) = res;
        }
    }
}

// ---------------------------------------------------------------------------
// Flash attention, fp32, register-blocked outer products.
// One CTA = 64 queries of one (n,h). 256 threads as 16x16 grid:
//   thread (ty = tid>>4, tx = tid&15) owns S/P rows 4ty..4ty+3 x cols 4tx..+3
//   and O rows 4ty..+3 x dh-dims 4tx..+3.
// smem: Qt (Q^T, swizzled) 16KB | Ks (K^T, swizzled; reused as P^T) 16KB |
//       Vs (natural [c][d]) 16KB  == 48KB static.
// ---------------------------------------------------------------------------
__global__ __launch_bounds__(256)
void flash_attn_kernel(const float* __restrict__ Qg, const float* __restrict__ Kg,
                       const float* __restrict__ Vg, const float* __restrict__ mbf,
                       float* __restrict__ Ag) {
    __shared__ float Qt[64 * 64];
    __shared__ float Ks[64 * 64];   // K^T during S, then P^T during PV
    __shared__ float Vs[64 * 64];

    const int n = blockIdx.z, h = blockIdx.y;
    const int q0 = blockIdx.x * 64;
    const size_t headBase = ((size_t)(n * NH + h)) * TT * DH;
    const float* Qb = Qg + headBase + (size_t)q0 * DH;
    const float* Kb = Kg + headBase;
    const float* Vb = Vg + headBase;
    const float* mb = mbf + (size_t)n * TT;

    const int tid = threadIdx.x;
    const int tx = tid & 15;
    const int ty = tid >> 4;

    // Load Q transposed (once): Qt[d][r] = Q[r][d], swizzled
    for (int idx = tid; idx < 1024; idx += 256) {
        int r  = idx >> 4;
        int d0 = (idx & 15) * 4;
        float4 v = *reinterpret_cast<const float4*>(&Qb[r * 64 + d0]);
        Qt[TIDX(d0 + 0, r)] = v.x;
        Qt[TIDX(d0 + 1, r)] = v.y;
        Qt[TIDX(d0 + 2, r)] = v.z;
        Qt[TIDX(d0 + 3, r)] = v.w;
    }
    __syncthreads();

    float o[4][4];
#pragma unroll
    for (int i = 0; i < 4; i++)
#pragma unroll
        for (int q = 0; q < 4; q++) o[i][q] = 0.0f;
    float mrow[4] = {-1e30f, -1e30f, -1e30f, -1e30f};
    float lrow[4] = {0.0f, 0.0f, 0.0f, 0.0f};
    const float sc = 0.125f;  // 1/sqrt(64)

    for (int kb = 0; kb < TT / 64; kb++) {
        const int c0 = kb * 64;
        // Skip fully-masked key tiles; barrier also protects Ks/Vs reuse.
        float mv = (tid < 64) ? mb[c0 + tid] : -1.0f;
        int alive = __syncthreads_count((tid < 64) && (mv == 0.0f));
        if (alive == 0) continue;

        // Load K transposed (swizzled) and V natural
        for (int idx = tid; idx < 1024; idx += 256) {
            int c  = idx >> 4;
            int d0 = (idx & 15) * 4;
            float4 kv = *reinterpret_cast<const float4*>(&Kb[(size_t)(c0 + c) * 64 + d0]);
            Ks[TIDX(d0 + 0, c)] = kv.x;
            Ks[TIDX(d0 + 1, c)] = kv.y;
            Ks[TIDX(d0 + 2, c)] = kv.z;
            Ks[TIDX(d0 + 3, c)] = kv.w;
            reinterpret_cast<float4*>(Vs)[idx] =
                reinterpret_cast<const float4*>(Vb + (size_t)c0 * 64)[idx];
        }
        __syncthreads();

        // S = Q K^T, 4x4 outer product per d
        float s[4][4];
#pragma unroll
        for (int i = 0; i < 4; i++)
#pragma unroll
            for (int q = 0; q < 4; q++) s[i][q] = 0.0f;

#pragma unroll 4
        for (int dg = 0; dg < 16; dg++) {
            const int sw = dg & 7;
            const float* qp = &Qt[dg * 256 + ((ty ^ sw) << 2)];
            const float* kp = &Ks[dg * 256 + ((tx ^ sw) << 2)];
#pragma unroll
            for (int j = 0; j < 4; j++) {
                float4 q4 = *reinterpret_cast<const float4*>(qp + j * 64);
                float4 k4 = *reinterpret_cast<const float4*>(kp + j * 64);
                float qr[4] = {q4.x, q4.y, q4.z, q4.w};
                float kr[4] = {k4.x, k4.y, k4.z, k4.w};
#pragma unroll
                for (int ri = 0; ri < 4; ri++)
#pragma unroll
                    for (int ci = 0; ci < 4; ci++) s[ri][ci] += qr[ri] * kr[ci];
            }
        }

        // scale + additive mask (per key column)
        float4 madd4 = *reinterpret_cast<const float4*>(&mb[c0 + 4 * tx]);
        float madd[4] = {madd4.x, madd4.y, madd4.z, madd4.w};
#pragma unroll
        for (int ri = 0; ri < 4; ri++)
#pragma unroll
            for (int ci = 0; ci < 4; ci++) s[ri][ci] = s[ri][ci] * sc + madd[ci];

        // Online softmax per row (reduce across the 16 tx threads of the row)
        float corr[4];
#pragma unroll
        for (int ri = 0; ri < 4; ri++) {
            float tmax = fmaxf(fmaxf(s[ri][0], s[ri][1]), fmaxf(s[ri][2], s[ri][3]));
            tmax = fmaxf(tmax, __shfl_xor_sync(0xffffffffu, tmax, 1));
            tmax = fmaxf(tmax, __shfl_xor_sync(0xffffffffu, tmax, 2));
            tmax = fmaxf(tmax, __shfl_xor_sync(0xffffffffu, tmax, 4));
            tmax = fmaxf(tmax, __shfl_xor_sync(0xffffffffu, tmax, 8));
            float mn = fmaxf(mrow[ri], tmax);
            corr[ri] = __expf(mrow[ri] - mn);
            float rs = 0.0f;
#pragma unroll
            for (int ci = 0; ci < 4; ci++) {
                float p = __expf(s[ri][ci] - mn);
                s[ri][ci] = p;
                rs += p;
            }
            rs += __shfl_xor_sync(0xffffffffu, rs, 1);
            rs += __shfl_xor_sync(0xffffffffu, rs, 2);
            rs += __shfl_xor_sync(0xffffffffu, rs, 4);
            rs += __shfl_xor_sync(0xffffffffu, rs, 8);
            lrow[ri] = lrow[ri] * corr[ri] + rs;
            mrow[ri] = mn;
#pragma unroll
            for (int di = 0; di < 4; di++) o[ri][di] *= corr[ri];
        }

        __syncthreads();  // all K^T reads done before overwriting Ks as P^T

        // Store P^T (swizzled): Pt[c][r] for c = 4tx+ci, r = 4ty..4ty+3
#pragma unroll
        for (int ci = 0; ci < 4; ci++) {
            int c = 4 * tx + ci;
            float4 pv = make_float4(s[0][ci], s[1][ci], s[2][ci], s[3][ci]);
            *reinterpret_cast<float4*>(&Ks[c * 64 + ((ty ^ (tx & 7)) << 2)]) = pv;
        }
        __syncthreads();

        // O += P @ V, 4x4 outer product per key c
#pragma unroll 4
        for (int cg = 0; cg < 16; cg++) {
            const int swp = ((ty ^ (cg & 7)) << 2);
#pragma unroll
            for (int j = 0; j < 4; j++) {
                const int c = cg * 4 + j;
                float4 p4 = *reinterpret_cast<const float4*>(&Ks[c * 64 + swp]);
                float4 v4 = *reinterpret_cast<const float4*>(&Vs[c * 64 + 4 * tx]);
                float pr[4] = {p4.x, p4.y, p4.z, p4.w};
                float vr[4] = {v4.x, v4.y, v4.z, v4.w};
#pragma unroll
                for (int ri = 0; ri < 4; ri++)
#pragma unroll
                    for (int di = 0; di < 4; di++) o[ri][di] += pr[ri] * vr[di];
            }
        }
        // next iteration's __syncthreads_count protects Ks/Vs reuse
    }

    // Normalize and write to [n, t, h*64 + d] (concat-head layout)
#pragma unroll
    for (int ri = 0; ri < 4; ri++) {
        float inv = 1.0f / lrow[ri];
        size_t obase = ((size_t)n * TT + q0 + 4 * ty + ri) * DM + h * DH + 4 * tx;
        float4 res;
        res.x = o[ri][0] * inv;
        res.y = o[ri][1] * inv;
        res.z = o[ri][2] * inv;
        res.w = o[ri][3] * inv;
        *reinterpret_cast<float4*>(&Ag[obase]) = res;
    }
}

// ---------------------------------------------------------------------------
// Launch
// ---------------------------------------------------------------------------
extern "C" void kernel_launch(void* const* d_in, const int* in_sizes, int n_in,
                              void* d_out, int out_size) {
    const float* x  = (const float*)d_in[0];
    const int*   mask = (const int*)d_in[1];
    const float* Wq = (const float*)d_in[2];
    const float* bq = (const float*)d_in[3];
    const float* Wk = (const float*)d_in[4];
    const float* bk = (const float*)d_in[5];
    const float* Wv = (const float*)d_in[6];
    const float* bv = (const float*)d_in[7];
    const float* Wo = (const float*)d_in[8];
    const float* bo = (const float*)d_in[9];
    float* out = (float*)d_out;

    float *q, *k, *v, *a, *mf;
    cudaGetSymbolAddress((void**)&q,  g_q);
    cudaGetSymbolAddress((void**)&k,  g_k);
    cudaGetSymbolAddress((void**)&v,  g_v);
    cudaGetSymbolAddress((void**)&a,  g_a);
    cudaGetSymbolAddress((void**)&mf, g_maskf);

    mask_to_f_kernel<<<(NB * TT + 255) / 256, 256>>>(mask, mf, NB * TT);

    dim3 ggrid(MROWS / 64, DM / 64);
    gemm_abt_kernel<1><<<ggrid, 256>>>(x, Wq, bq, q);
    gemm_abt_kernel<1><<<ggrid, 256>>>(x, Wk, bk, k);
    gemm_abt_kernel<1><<<ggrid, 256>>>(x, Wv, bv, v);

    dim3 agrid(TT / 64, NH, NB);
    flash_attn_kernel<<<agrid, 256>>>(q, k, v, mf, a);

    gemm_abt_kernel<0><<<ggrid, 256>>>(a, Wo, bo, out);
}